// round 8
// baseline (speedup 1.0000x reference)
#include <cuda_runtime.h>
#include <cuda_bf16.h>

#define S_DIM 128
#define A_DIM 96
#define B_DIM 256
#define LX    512
#define LY    256
#define XOFF_STRIDE 584   // padded clamped xs byte-offset table per batch

// Per-batch gathered cost table: Gt[b][x][j] = (-softmax(P)[x] - 1)[ys[b][j]]
__device__ float g_Gt[(size_t)B_DIM * S_DIM * LY];
// xoff[b][t] = xs[b][clamp(t-32, 0, xl-1)] * 1024  (byte row offset in Gt)
__device__ int   g_xoff[B_DIM * XOFF_STRIDE];

// One block per batch: compute softmax table in smem (8 warps x 16 rows),
// then build Gt[b] (coalesced gather) and xoff[b]. Fused: no separate
// softmax kernel, no global round-trip for the 48KB table.
__global__ void build_kernel(const float* __restrict__ P,
                             const int* __restrict__ xs,
                             const int* __restrict__ ys,
                             const int* __restrict__ xlen) {
    __shared__ float sC[S_DIM * A_DIM];
    const int b    = blockIdx.x;
    const int tid  = threadIdx.x;
    const int wid  = tid >> 5;
    const int lane = tid & 31;

    // softmax rows: warp w handles rows w, w+8, ... (3 cols per lane)
    for (int row = wid; row < S_DIM; row += 8) {
        const float* pr = P + row * A_DIM;
        float v0 = pr[lane], v1 = pr[lane + 32], v2 = pr[lane + 64];
        float m = fmaxf(v0, fmaxf(v1, v2));
        #pragma unroll
        for (int o = 16; o > 0; o >>= 1) m = fmaxf(m, __shfl_xor_sync(0xffffffffu, m, o));
        float e0 = expf(v0 - m), e1 = expf(v1 - m), e2 = expf(v2 - m);
        float s = e0 + e1 + e2;
        #pragma unroll
        for (int o = 16; o > 0; o >>= 1) s += __shfl_xor_sync(0xffffffffu, s, o);
        float inv = -1.0f / s;
        sC[row * A_DIM + lane     ] = e0 * inv - 1.0f;   // c'' = -softmax - 1
        sC[row * A_DIM + lane + 32] = e1 * inv - 1.0f;
        sC[row * A_DIM + lane + 64] = e2 * inv - 1.0f;
    }

    // xoff table (independent of sC)
    const int xl   = xlen[b] - 1;
    const int xcap = xl - 1;
    const int* xsb = xs + (size_t)b * LX;
    for (int t = tid; t < XOFF_STRIDE; t += 256) {
        int q = t - 32;
        int v = min(max(q, 0), xcap);
        g_xoff[b * XOFF_STRIDE + t] = xsb[v] * (LY * 4);
    }
    __syncthreads();

    const int yj = ys[(size_t)b * LY + tid];
    float* ob = g_Gt + (size_t)b * S_DIM * LY + tid;
    #pragma unroll 4
    for (int x = 0; x < S_DIM; ++x)
        ob[x * LY] = sC[x * A_DIM + yj];
}

// One warp per batch, lane-skewed wavefront, D'' = D - j - r space.
//   E''[j]   = min(D''_{r-1}[j], D''_{r-1}[j-1] + c'')
//   D''_r[j] = min(prefixmin(E'')[j], D''_r[8L])     (lane-0 boundary = 0)
// Prefix-min folded with the boundary commit via half-serial prefixes:
// 22 FMNMX/step (alu-pipe is the issue floor). out = D'' + xl + yl.

#define DP_STEP(COMMIT) do {                                                   \
    /* prefetch costs for step s+4 (xo0 = xoff byte offset) */                 \
    const char* rp_ = Gtb + xo0;                                               \
    float4 nA_ = *(const float4*)rp_;                                          \
    float4 nB_ = *(const float4*)(rp_ + 16);                                   \
    int xnew_ = *xpr; ++xpr;       /* xoff for step s+8 */                     \
    float Dl_eff = is0 ? 0.0f : Dl;                                            \
    float E0_ = fminf(D[0], bprev + cA[0].x);                                  \
    float E1_ = fminf(D[1], D[0] + cA[0].y);                                   \
    float E2_ = fminf(D[2], D[1] + cA[0].z);                                   \
    float E3_ = fminf(D[3], D[2] + cA[0].w);                                   \
    float E4_ = fminf(D[4], D[3] + cB[0].x);                                   \
    float E5_ = fminf(D[5], D[4] + cB[0].y);                                   \
    float E6_ = fminf(D[6], D[5] + cB[0].z);                                   \
    float E7_ = fminf(D[7], D[6] + cB[0].w);                                   \
    float p1_ = fminf(E0_, E1_);                                               \
    float p2_ = fminf(p1_, E2_);                                               \
    float p3_ = fminf(p2_, E3_);                                               \
    float q5_ = fminf(E4_, E5_);                                               \
    float q6_ = fminf(q5_, E6_);                                               \
    float q7_ = fminf(q6_, E7_);                                               \
    if (COMMIT) {                                                              \
        D[0] = fminf(E0_, Dl_eff);                                             \
        D[1] = fminf(p1_, Dl_eff);                                             \
        D[2] = fminf(p2_, Dl_eff);                                             \
        D[3] = fminf(p3_, Dl_eff);                                             \
        D[4] = fminf(E4_, D[3]);                                               \
        D[5] = fminf(q5_, D[3]);                                               \
        D[6] = fminf(q6_, D[3]);                                               \
        D[7] = fminf(q7_, D[3]);                                               \
    }                                                                          \
    float sh_ = __shfl_up_sync(0xffffffffu, D[7], 1);                          \
    bprev = Dl_eff;                                                            \
    Dl    = sh_;                                                               \
    cA[0] = cA[1]; cA[1] = cA[2]; cA[2] = cA[3]; cA[3] = nA_;                  \
    cB[0] = cB[1]; cB[1] = cB[2]; cB[2] = cB[3]; cB[3] = nB_;                  \
    xo0 = xo1; xo1 = xo2; xo2 = xo3; xo3 = xnew_;                              \
} while (0)

__global__ void __launch_bounds__(32, 4) dp_kernel(
    const int* __restrict__ xlen,
    const int* __restrict__ ylen,
    float* __restrict__ out)
{
    const int b    = blockIdx.x;
    const int lane = threadIdx.x;
    const int xl   = xlen[b] - 1;   // target row (1..511)
    const int yl   = ylen[b] - 1;   // target col (1..255)

    const char* Gtb = (const char*)(g_Gt + (size_t)b * S_DIM * LY) + lane * 32;
    const int*  xpb = g_xoff + b * XOFF_STRIDE;

    const int t_lane = (yl - 1) >> 3;
    const int k_t    = (yl - 1) & 7;
    const int s_end  = xl + t_lane;
    const bool is0   = (lane == 0);

    float D[8];
    #pragma unroll
    for (int k = 0; k < 8; ++k) D[k] = 0.0f;   // row 0: D'' = 0

    float Dl = 0.0f, bprev = 0.0f;

    // prefill cost pipeline
    float4 cA[4], cB[4];
    #pragma unroll
    for (int p = 0; p < 4; ++p) {
        int xv = xpb[32 - lane + p];            // steps 1..4
        const char* r = Gtb + xv;
        cA[p] = *(const float4*)r;
        cB[p] = *(const float4*)(r + 16);
    }
    int xo0 = xpb[36 - lane];                   // step 5
    int xo1 = xpb[37 - lane];
    int xo2 = xpb[38 - lane];
    int xo3 = xpb[39 - lane];
    const int* xpr = xpb + 40 - lane;           // step 9 onward

    int s = 1;
    const int rampEnd = min(31, s_end);
    #pragma unroll 4
    for (; s <= rampEnd; ++s) {
        const bool act = (s > lane);
        DP_STEP(act);
    }
    #pragma unroll 4
    for (; s <= s_end; ++s) {
        DP_STEP(true);
    }

    if (lane == t_lane) out[b] = D[k_t] + (float)(xl + yl);
}

extern "C" void kernel_launch(void* const* d_in, const int* in_sizes, int n_in,
                              void* d_out, int out_size) {
    const float* P    = (const float*)d_in[0];
    const int*   xs   = (const int*)d_in[1];
    const int*   ys   = (const int*)d_in[2];
    const int*   xlen = (const int*)d_in[3];
    const int*   ylen = (const int*)d_in[4];
    float*       out  = (float*)d_out;

    build_kernel<<<B_DIM, 256>>>(P, xs, ys, xlen);
    dp_kernel<<<B_DIM, 32>>>(xlen, ylen, out);
}